// round 3
// baseline (speedup 1.0000x reference)
#include <cuda_runtime.h>
#include <cuda_fp16.h>

#define Nn 50000
#define Ee 1000000
#define INC 128
#define NHEADS 4
#define OUTC 16
#define HID 64
#define BM 128

// ---------------- device scratch (no allocations allowed) ----------------
__device__ __half g_projh[Nn * HID];     // 6.4 MB, fp16 copy for the edge gather
__device__ float  g_asrc[Nn * NHEADS];
__device__ float  g_adst[Nn * NHEADS];
__device__ float  g_s   [Nn * NHEADS];   // softmax denominator (seeded w/ self-loop)

__device__ __forceinline__ float lrelu(float x) { return x > 0.f ? x : 0.2f * x; }

// ---------------- K1: proj = x @ W^T + fused attention epilogue ------------
// 128x64 block tile, 128 threads, 8x8 microtile (4 LDS.128 per 64 FMA).
// Epilogue: per-(row,head) att dots (shfl over 2 lanes), seeds g_s with the
// self-loop exp, writes fp16 proj and the self-loop contribution es*proj.
__global__ void gemm_fused_kernel(const float* __restrict__ x, const float* __restrict__ W,
                                  const float* __restrict__ att_src,
                                  const float* __restrict__ att_dst,
                                  float* __restrict__ out) {
    __shared__ float As[16][BM + 4];   // [k][m]
    __shared__ float Bs[16][68];       // [k][o]
    const int t  = threadIdx.x;        // 0..127
    const int bm = blockIdx.x * BM;
    const int tm = t >> 3, tn = t & 7;
    const int rm = tm * 8, rn = tn * 8;
    const int lrB = t & 63, kb = (t >> 6) * 8;

    float acc[8][8];
#pragma unroll
    for (int i = 0; i < 8; i++)
#pragma unroll
        for (int j = 0; j < 8; j++) acc[i][j] = 0.f;

    for (int kc = 0; kc < INC; kc += 16) {
        // A: thread t owns row (bm+t), loads 16 k-values
        const int gr = bm + t;
        float4 av[4];
#pragma unroll
        for (int j = 0; j < 4; j++)
            av[j] = (gr < Nn) ? *(const float4*)(x + gr * INC + kc + j * 4)
                              : make_float4(0.f, 0.f, 0.f, 0.f);
#pragma unroll
        for (int j = 0; j < 4; j++) {
            As[j * 4 + 0][t] = av[j].x; As[j * 4 + 1][t] = av[j].y;
            As[j * 4 + 2][t] = av[j].z; As[j * 4 + 3][t] = av[j].w;
        }
        // B: two threads per output row, 8 k-values each
        const float4 bv0 = *(const float4*)(W + lrB * INC + kc + kb);
        const float4 bv1 = *(const float4*)(W + lrB * INC + kc + kb + 4);
        Bs[kb + 0][lrB] = bv0.x; Bs[kb + 1][lrB] = bv0.y;
        Bs[kb + 2][lrB] = bv0.z; Bs[kb + 3][lrB] = bv0.w;
        Bs[kb + 4][lrB] = bv1.x; Bs[kb + 5][lrB] = bv1.y;
        Bs[kb + 6][lrB] = bv1.z; Bs[kb + 7][lrB] = bv1.w;
        __syncthreads();

#pragma unroll
        for (int kk = 0; kk < 16; kk++) {
            const float4 a0 = *(const float4*)&As[kk][rm];
            const float4 a1 = *(const float4*)&As[kk][rm + 4];
            const float4 b0 = *(const float4*)&Bs[kk][rn];
            const float4 b1 = *(const float4*)&Bs[kk][rn + 4];
            const float aa[8] = {a0.x, a0.y, a0.z, a0.w, a1.x, a1.y, a1.z, a1.w};
            const float bb[8] = {b0.x, b0.y, b0.z, b0.w, b1.x, b1.y, b1.z, b1.w};
#pragma unroll
            for (int i = 0; i < 8; i++)
#pragma unroll
                for (int j = 0; j < 8; j++) acc[i][j] += aa[i] * bb[j];
        }
        __syncthreads();
    }

    // ---- fused epilogue ----
    const int head = tn >> 1;                 // 16 cols per head, thread owns 8
    const int coff = (tn & 1) * 8;
    const float4 vs0 = *(const float4*)(att_src + head * OUTC + coff);
    const float4 vs1 = *(const float4*)(att_src + head * OUTC + coff + 4);
    const float4 vd0 = *(const float4*)(att_dst + head * OUTC + coff);
    const float4 vd1 = *(const float4*)(att_dst + head * OUTC + coff + 4);
    const float vsa[8] = {vs0.x, vs0.y, vs0.z, vs0.w, vs1.x, vs1.y, vs1.z, vs1.w};
    const float vda[8] = {vd0.x, vd0.y, vd0.z, vd0.w, vd1.x, vd1.y, vd1.z, vd1.w};

#pragma unroll
    for (int i = 0; i < 8; i++) {
        float s1 = 0.f, s2 = 0.f;
#pragma unroll
        for (int j = 0; j < 8; j++) { s1 += acc[i][j] * vsa[j]; s2 += acc[i][j] * vda[j]; }
        // reduce over the 2 lanes sharing (row, head)
        s1 += __shfl_xor_sync(0xffffffffu, s1, 1);
        s2 += __shfl_xor_sync(0xffffffffu, s2, 1);

        const int gr = bm + rm + i;
        if (gr < Nn) {
            const float es = __expf(lrelu(s1 + s2));     // self-loop weight
            if ((tn & 1) == 0) {
                g_asrc[gr * 4 + head] = s1;
                g_adst[gr * 4 + head] = s2;
                g_s   [gr * 4 + head] = es;
            }
            // fp16 proj (for edge gather)
            uint4 hp;
            ((__half2*)&hp)[0] = __floats2half2_rn(acc[i][0], acc[i][1]);
            ((__half2*)&hp)[1] = __floats2half2_rn(acc[i][2], acc[i][3]);
            ((__half2*)&hp)[2] = __floats2half2_rn(acc[i][4], acc[i][5]);
            ((__half2*)&hp)[3] = __floats2half2_rn(acc[i][6], acc[i][7]);
            *(uint4*)(g_projh + gr * HID + rn) = hp;
            // self-loop seed (exact fp32)
            *(float4*)(out + gr * HID + rn) =
                make_float4(es * acc[i][0], es * acc[i][1], es * acc[i][2], es * acc[i][3]);
            *(float4*)(out + gr * HID + rn + 4) =
                make_float4(es * acc[i][4], es * acc[i][5], es * acc[i][6], es * acc[i][7]);
        }
    }
}

// ---------------- K2: per-edge exp + vector-reduce scatter ----------------
// 16 lanes per edge; each lane owns 4 channels. fp16 gather (128B/edge),
// fp32 red.v4 scatter. No max subtraction (softmax shift-invariant; logits
// bounded, exp stays in fp32 range).
__global__ void edge_accum_kernel(const int* __restrict__ ei, float* __restrict__ out) {
    const int gt = blockIdx.x * blockDim.x + threadIdx.x;
    const int e = gt >> 4;
    if (e >= Ee) return;
    const int q = gt & 15;          // channel group 0..15
    const int h = q >> 2;           // head
    const int r = ei[e], c = ei[Ee + e];
    const float as = g_asrc[r * 4 + h];
    const float ad = g_adst[c * 4 + h];
    const float ev = __expf(lrelu(as + ad));
    if ((q & 3) == 0) atomicAdd(g_s + c * 4 + h, ev);
    const uint2 ph = ((const uint2*)g_projh)[r * 16 + q];   // 4 halves
    const float2 f01 = __half22float2(*(const __half2*)&ph.x);
    const float2 f23 = __half22float2(*(const __half2*)&ph.y);
    float* dst = out + c * HID + q * 4;
    asm volatile("red.global.add.v4.f32 [%0], {%1,%2,%3,%4};"
                 :: "l"(dst), "f"(ev * f01.x), "f"(ev * f01.y),
                    "f"(ev * f23.x), "f"(ev * f23.y)
                 : "memory");
}

// ---------------- K3: normalize + bias ----------------
__global__ void final_kernel(float* __restrict__ out, const float* __restrict__ bias) {
    const int i = blockIdx.x * blockDim.x + threadIdx.x;   // n*16 + q
    if (i >= Nn * 16) return;
    const int n = i >> 4, h = (i >> 2) & 3;
    const float inv = 1.0f / g_s[n * 4 + h];
    const float4 o = ((const float4*)out)[i];
    const float4 b = ((const float4*)bias)[i & 15];
    ((float4*)out)[i] = make_float4(o.x * inv + b.x, o.y * inv + b.y,
                                    o.z * inv + b.z, o.w * inv + b.w);
}

// ---------------- launch ----------------
extern "C" void kernel_launch(void* const* d_in, const int* in_sizes, int n_in,
                              void* d_out, int out_size) {
    const float* x       = (const float*)d_in[0];
    const int*   ei      = (const int*)  d_in[1];
    const float* W       = (const float*)d_in[2];
    const float* att_src = (const float*)d_in[3];
    const float* att_dst = (const float*)d_in[4];
    const float* bias    = (const float*)d_in[5];
    float* out = (float*)d_out;

    gemm_fused_kernel<<<(Nn + BM - 1) / BM, 128>>>(x, W, att_src, att_dst, out);
    edge_accum_kernel<<<(Ee * 16 + 255) / 256, 256>>>(ei, out);
    final_kernel     <<<(Nn * 16 + 255) / 256, 256>>>(out, bias);
}